// round 3
// baseline (speedup 1.0000x reference)
#include <cuda_runtime.h>
#include <cstdint>

// trans_b: [32, 64, 256, 256] fp32 = 2048 planes x 65536 elems
#define NPLANES          2048
#define PLANE_F4         16384      // 65536/4
#define NBLOCKS          592        // 4 per SM on 148 SMs -> single wave, resident
#define NTHREADS         256
#define ROUNDS           8
#define BATCHES_PER_RND  4
#define PLANES_PER_RND   256        // 4 batches * 64 channels (67 MB/round, fits L2)
#define CHUNKS_PER_PLANE 4
#define CHUNK_F4         4096       // PLANE_F4/4
#define CHUNKS_PER_RND   1024       // PLANES_PER_RND * CHUNKS_PER_PLANE

__device__ float    g_pooled[NPLANES];   // raw plane sums
__device__ float    g_scale[NPLANES];
__device__ unsigned g_cnt;               // barrier arrivals (self-resets to 0)
__device__ unsigned g_gen;               // barrier generation (monotonic, replay-safe)

// Software grid barrier. Safe because the grid is exactly one resident wave.
// Generation flag is compared relatively, so it never needs resetting across
// graph replays; the counter is reset by the last arriver before the flag flip.
__device__ __forceinline__ void grid_barrier()
{
    __syncthreads();
    if (threadIdx.x == 0) {
        __threadfence();                             // publish this block's writes
        unsigned gen = atomicAdd(&g_gen, 0u);        // read gen BEFORE arriving
        if (atomicAdd(&g_cnt, 1u) == NBLOCKS - 1u) {
            atomicExch(&g_cnt, 0u);                  // reset counter first
            __threadfence();
            atomicAdd(&g_gen, 1u);                   // then release everyone
        } else {
            while (atomicAdd(&g_gen, 0u) == gen)
                __nanosleep(64);
        }
        __threadfence();                             // acquire
    }
    __syncthreads();
}

__global__ void __launch_bounds__(NTHREADS, 4) se_fused_kernel(
    const float* __restrict__ x, float* __restrict__ y,
    const float* __restrict__ w_down,  // [4,64]
    const float* __restrict__ b_down,  // [4]
    const float* __restrict__ w_up,    // [64,4]
    const float* __restrict__ b_up)    // [64]
{
    const int tid = threadIdx.x;
    __shared__ float sred[8];

    // Zero plane accumulators (fresh every launch / graph replay).
    for (int i = blockIdx.x * NTHREADS + tid; i < NPLANES; i += NBLOCKS * NTHREADS)
        g_pooled[i] = 0.0f;
    grid_barrier();

    for (int r = 0; r < ROUNDS; r++) {
        // ---- Phase 1: pool this round's 4 batches (67 MB -> L2) ----------
        for (int c = blockIdx.x; c < CHUNKS_PER_RND; c += NBLOCKS) {
            const int plane = r * PLANES_PER_RND + (c >> 2);
            const float4* __restrict__ p = reinterpret_cast<const float4*>(x)
                + (size_t)plane * PLANE_F4 + (size_t)(c & 3) * CHUNK_F4;

            float sum = 0.0f;
            #pragma unroll 16
            for (int i = tid; i < CHUNK_F4; i += NTHREADS) {
                float4 v = __ldcg(p + i);            // fill L2, skip L1
                sum += (v.x + v.y) + (v.z + v.w);
            }
            #pragma unroll
            for (int o = 16; o > 0; o >>= 1)
                sum += __shfl_xor_sync(0xFFFFFFFFu, sum, o);
            if ((tid & 31) == 0) sred[tid >> 5] = sum;
            __syncthreads();
            if (tid < 32) {
                sum = (tid < 8) ? sred[tid] : 0.0f;
                #pragma unroll
                for (int o = 4; o > 0; o >>= 1)
                    sum += __shfl_xor_sync(0xFFFFFFFFu, sum, o);
                if (tid == 0) atomicAdd(&g_pooled[plane], sum);
            }
            __syncthreads();                          // sred reuse across chunks
        }
        grid_barrier();

        // ---- Phase 2: MLP for the 4 batches (blocks 0..3) ----------------
        if (blockIdx.x < BATCHES_PER_RND && tid < 64) {
            const int b = r * BATCHES_PER_RND + blockIdx.x;
            float h0 = b_down[0], h1 = b_down[1], h2 = b_down[2], h3 = b_down[3];
            #pragma unroll 8
            for (int k = 0; k < 64; k++) {
                float pk = g_pooled[b * 64 + k] * (1.0f / 65536.0f);
                h0 = fmaf(pk, w_down[0 * 64 + k], h0);
                h1 = fmaf(pk, w_down[1 * 64 + k], h1);
                h2 = fmaf(pk, w_down[2 * 64 + k], h2);
                h3 = fmaf(pk, w_down[3 * 64 + k], h3);
            }
            h0 = fmaxf(h0, 0.0f); h1 = fmaxf(h1, 0.0f);
            h2 = fmaxf(h2, 0.0f); h3 = fmaxf(h3, 0.0f);
            float s = b_up[tid];
            s = fmaf(h0, w_up[tid * 4 + 0], s);
            s = fmaf(h1, w_up[tid * 4 + 1], s);
            s = fmaf(h2, w_up[tid * 4 + 2], s);
            s = fmaf(h3, w_up[tid * 4 + 3], s);
            g_scale[b * 64 + tid] = 1.0f / (1.0f + expf(-s));
        }
        grid_barrier();

        // ---- Phase 3: rescale; reads should hit L2, writes stream out ----
        for (int c = blockIdx.x; c < CHUNKS_PER_RND; c += NBLOCKS) {
            const int plane = r * PLANES_PER_RND + (c >> 2);
            const float s = g_scale[plane];
            const size_t base = (size_t)plane * PLANE_F4 + (size_t)(c & 3) * CHUNK_F4;
            const float4* __restrict__ px = reinterpret_cast<const float4*>(x) + base;
            float4* __restrict__ py = reinterpret_cast<float4*>(y) + base;

            #pragma unroll 8
            for (int i = tid; i < CHUNK_F4; i += NTHREADS) {
                float4 v = __ldcg(px + i);           // L2 hit (pooled this round)
                v.x *= s; v.y *= s; v.z *= s; v.w *= s;
                __stcs(py + i, v);                   // evict-first: protect reads
            }
        }
        // No barrier needed here: next round touches disjoint planes, and its
        // g_pooled slots were zeroed at kernel entry.
    }
}

extern "C" void kernel_launch(void* const* d_in, const int* in_sizes, int n_in,
                              void* d_out, int out_size)
{
    const float* trans_b = (const float*)d_in[0];
    const float* w_down  = (const float*)d_in[1];
    const float* b_down  = (const float*)d_in[2];
    const float* w_up    = (const float*)d_in[3];
    const float* b_up    = (const float*)d_in[4];
    float* out = (float*)d_out;

    se_fused_kernel<<<NBLOCKS, NTHREADS>>>(trans_b, out, w_down, b_down, w_up, b_up);
}

// round 4
// speedup vs baseline: 1.0274x; 1.0274x over previous
#include <cuda_runtime.h>
#include <cstdint>

// trans_b: [32, 64, 256, 256] fp32 = 2048 planes x 16384 float4
#define NPLANES          2048
#define PLANE_F4         16384
#define NBLOCKS          512
#define NTHREADS         512
#define ROUNDS           8
#define PLANES_PER_RND   256            // 4 batches x 64 ch = 67 MB/round (fits L2)
#define ROUND_F4         4194304        // 256 * 16384
#define CHUNK_F4         2048           // 8 chunks per plane
#define CHUNKS_PER_RND   2048           // = 4 chunks per block, exact
#define SCALE_ITERS      16             // ROUND_F4 / (NBLOCKS*NTHREADS), exact

__device__ float    g_partial[NPLANES * 8];   // per-chunk partial sums
__device__ unsigned g_cnt;                    // barrier arrivals (self-resets)
__device__ unsigned g_gen;                    // barrier generation (monotonic)

// Grid barrier: safe because grid is one resident wave (launch_bounds(512,4)
// guarantees residency of all 512 blocks on 148 SMs). Generation compared
// relatively -> replay-safe, no per-launch reset needed.
__device__ __forceinline__ void grid_barrier()
{
    __threadfence();                         // publish each thread's writes
    __syncthreads();
    if (threadIdx.x == 0) {
        unsigned gen = atomicAdd(&g_gen, 0u);
        if (atomicAdd(&g_cnt, 1u) == NBLOCKS - 1u) {
            atomicExch(&g_cnt, 0u);
            __threadfence();
            atomicAdd(&g_gen, 1u);
        } else {
            while (atomicAdd(&g_gen, 0u) == gen)
                __nanosleep(32);
        }
    }
    __syncthreads();
}

__global__ void __launch_bounds__(NTHREADS, 4) se_fused_kernel(
    const float* __restrict__ x, float* __restrict__ y,
    const float* __restrict__ w_down,  // [4,64]
    const float* __restrict__ b_down,  // [4]
    const float* __restrict__ w_up,    // [64,4]
    const float* __restrict__ b_up)    // [64]
{
    const int tid = threadIdx.x;
    __shared__ float sred[16];
    __shared__ float s_pooled[256];
    __shared__ float s_scale[256];

    for (int r = 0; r < ROUNDS; r++) {
        // ---- Phase 1: pool. 4 chunks per block, partial sums -> g_partial.
        #pragma unroll
        for (int k = 0; k < 4; k++) {
            const int gc = r * CHUNKS_PER_RND + blockIdx.x + k * NBLOCKS;
            const float4* __restrict__ p =
                reinterpret_cast<const float4*>(x) + (size_t)gc * CHUNK_F4;

            float sum = 0.0f;
            #pragma unroll
            for (int i = tid; i < CHUNK_F4; i += NTHREADS) {
                float4 v = __ldcg(p + i);            // fill L2, skip L1
                sum += (v.x + v.y) + (v.z + v.w);
            }
            #pragma unroll
            for (int o = 16; o > 0; o >>= 1)
                sum += __shfl_xor_sync(0xFFFFFFFFu, sum, o);
            if ((tid & 31) == 0) sred[tid >> 5] = sum;
            __syncthreads();
            if (tid < 32) {
                sum = (tid < 16) ? sred[tid] : 0.0f;
                #pragma unroll
                for (int o = 8; o > 0; o >>= 1)
                    sum += __shfl_xor_sync(0xFFFFFFFFu, sum, o);
                if (tid == 0) g_partial[gc] = sum;   // gc == plane*8 + chunk
            }
            __syncthreads();
        }
        grid_barrier();                               // all partials visible

        // ---- Phase 2 (per-block, redundant): assemble pooled means + MLP.
        if (tid < 256) {
            const float* pp = g_partial + (size_t)(r * PLANES_PER_RND + tid) * 8;
            float a = 0.0f;
            #pragma unroll
            for (int j = 0; j < 8; j++)               // fixed order: deterministic
                a += __ldcg(pp + j);
            s_pooled[tid] = a * (1.0f / 65536.0f);
        }
        __syncthreads();
        if (tid < 256) {
            const int bl = tid >> 6;                  // round-local batch 0..3
            const int c  = tid & 63;
            float h0 = b_down[0], h1 = b_down[1], h2 = b_down[2], h3 = b_down[3];
            #pragma unroll 8
            for (int k = 0; k < 64; k++) {
                const float pk = s_pooled[bl * 64 + k];
                h0 = fmaf(pk, w_down[0 * 64 + k], h0);
                h1 = fmaf(pk, w_down[1 * 64 + k], h1);
                h2 = fmaf(pk, w_down[2 * 64 + k], h2);
                h3 = fmaf(pk, w_down[3 * 64 + k], h3);
            }
            h0 = fmaxf(h0, 0.0f); h1 = fmaxf(h1, 0.0f);
            h2 = fmaxf(h2, 0.0f); h3 = fmaxf(h3, 0.0f);
            float s = b_up[c];
            s = fmaf(h0, w_up[c * 4 + 0], s);
            s = fmaf(h1, w_up[c * 4 + 1], s);
            s = fmaf(h2, w_up[c * 4 + 2], s);
            s = fmaf(h3, w_up[c * 4 + 3], s);
            s_scale[tid] = 1.0f / (1.0f + expf(-s));
        }
        __syncthreads();

        // ---- Phase 3: rescale. Flat, perfectly balanced, reads hit L2.
        {
            size_t idx = (size_t)r * ROUND_F4 + (size_t)blockIdx.x * NTHREADS + tid;
            const float4* __restrict__ px = reinterpret_cast<const float4*>(x);
            float4*       __restrict__ py = reinterpret_cast<float4*>(y);
            #pragma unroll 4
            for (int it = 0; it < SCALE_ITERS; it++) {
                const float s = s_scale[(idx >> 14) & 255];
                float4 v = __ldcg(px + idx);          // L2 hit (pooled this round)
                v.x *= s; v.y *= s; v.z *= s; v.w *= s;
                __stcs(py + idx, v);                  // evict-first stores
                idx += (size_t)NBLOCKS * NTHREADS;
            }
        }
        // No barrier: next round's pool writes disjoint g_partial slots and
        // reads disjoint planes; s_pooled/s_scale are block-local and resynced.
    }
}

extern "C" void kernel_launch(void* const* d_in, const int* in_sizes, int n_in,
                              void* d_out, int out_size)
{
    const float* trans_b = (const float*)d_in[0];
    const float* w_down  = (const float*)d_in[1];
    const float* b_down  = (const float*)d_in[2];
    const float* w_up    = (const float*)d_in[3];
    const float* b_up    = (const float*)d_in[4];
    float* out = (float*)d_out;

    se_fused_kernel<<<NBLOCKS, NTHREADS>>>(trans_b, out, w_down, b_down, w_up, b_up);
}

// round 5
// speedup vs baseline: 1.2808x; 1.2467x over previous
#include <cuda_runtime.h>
#include <cstdint>

// trans_b: [32, 64, 256, 256] fp32 = 2048 planes x 16384 float4
#define NPLANES        2048
#define PLANE_F4       16384
#define NBLOCKS        512
#define NTHREADS       512
#define ROUNDS         8
#define PLANES_PER_RND 256          // 4 batches x 64 ch = 67 MB/round (fits L2)
#define POOL_UNITS     1024         // quarter-planes per round (64 KB each)
#define QUARTER_F4     4096
#define SCALE_UNITS    2048         // 32 KB units per round
#define SCALE_UNIT_F4  2048

__device__ float    g_partial[ROUNDS * POOL_UNITS];  // per-quarter sums
__device__ unsigned g_ticket_pool[ROUNDS];
__device__ unsigned g_ticket_scale[ROUNDS];
__device__ unsigned g_done[ROUNDS];
__device__ unsigned g_cnt, g_gen;   // entry barrier (replay-safe generation)

// One entry barrier per launch: publishes the counter resets. Generation is
// compared relatively, so no cross-replay reset is needed for g_cnt/g_gen.
__device__ __forceinline__ void entry_barrier()
{
    __syncthreads();
    if (threadIdx.x == 0) {
        __threadfence();
        unsigned gen = atomicAdd(&g_gen, 0u);
        if (atomicAdd(&g_cnt, 1u) == NBLOCKS - 1u) {
            atomicExch(&g_cnt, 0u);
            __threadfence();
            atomicAdd(&g_gen, 1u);
        } else {
            while (atomicAdd(&g_gen, 0u) == gen) __nanosleep(32);
        }
        __threadfence();
    }
    __syncthreads();
}

__global__ void __launch_bounds__(NTHREADS, 4) se_fused_kernel(
    const float* __restrict__ x, float* __restrict__ y,
    const float* __restrict__ w_down,  // [4,64]
    const float* __restrict__ b_down,  // [4]
    const float* __restrict__ w_up,    // [64,4]
    const float* __restrict__ b_up)    // [64]
{
    const int tid = threadIdx.x;
    const float4* __restrict__ px = reinterpret_cast<const float4*>(x);
    float4*       __restrict__ py = reinterpret_cast<float4*>(y);

    __shared__ float    sred[16];
    __shared__ float    s_pooled[256];
    __shared__ float    s_scale[256];
    __shared__ float    s_wdown[256], s_wup[256], s_bup[64], s_bdown[4];
    __shared__ float    s_hp[8][4];     // per-warp hidden partials
    __shared__ float    s_h[4][4];      // relu(hidden) per round-local batch
    __shared__ unsigned s_u;

    // Stage tiny weights once.
    if (tid < 256) { s_wdown[tid] = w_down[tid]; s_wup[tid] = w_up[tid]; }
    if (tid < 64)  s_bup[tid] = b_up[tid];
    if (tid < 4)   s_bdown[tid] = b_down[tid];

    // Reset per-launch counters (block 0), publish via entry barrier.
    if (blockIdx.x == 0 && tid < 3 * ROUNDS) {
        if (tid < ROUNDS)           g_ticket_pool[tid] = 0u;
        else if (tid < 2 * ROUNDS)  g_ticket_scale[tid - ROUNDS] = 0u;
        else                        g_done[tid - 2 * ROUNDS] = 0u;
    }
    entry_barrier();

    for (int r = 0; r < ROUNDS; r++) {
        // ================= Phase 1: pool (dynamic quarter-planes) =========
        for (;;) {
            if (tid == 0) s_u = atomicAdd(&g_ticket_pool[r], 1u);
            __syncthreads();
            const unsigned u = s_u;
            __syncthreads();                 // s_u / sred safe for reuse
            if (u >= POOL_UNITS) break;

            const float4* __restrict__ p = px
                + ((size_t)(r * PLANES_PER_RND + (u >> 2)) << 14)
                + ((size_t)(u & 3) << 12);

            float sum = 0.0f;
            #pragma unroll
            for (int i = 0; i < 8; i++) {    // 8 front-batched loads, MLP=8
                float4 v = __ldcg(p + tid + i * NTHREADS);
                sum += (v.x + v.y) + (v.z + v.w);
            }
            #pragma unroll
            for (int o = 16; o > 0; o >>= 1)
                sum += __shfl_xor_sync(0xFFFFFFFFu, sum, o);
            if ((tid & 31) == 0) sred[tid >> 5] = sum;
            __syncthreads();
            if (tid < 32) {
                sum = (tid < 16) ? sred[tid] : 0.0f;
                #pragma unroll
                for (int o = 8; o > 0; o >>= 1)
                    sum += __shfl_xor_sync(0xFFFFFFFFu, sum, o);
                if (tid == 0) {
                    __stcg(&g_partial[r * POOL_UNITS + u], sum);
                    __threadfence();
                    atomicAdd(&g_done[r], 1u);
                }
            }
        }

        // ============ Wait for round's pooling, then per-block MLP ========
        if (tid == 0) {
            while (atomicAdd(&g_done[r], 0u) < POOL_UNITS) __nanosleep(32);
            __threadfence();
        }
        __syncthreads();

        if (tid < 256) {                     // assemble means (fixed order)
            const float* pp = g_partial + r * POOL_UNITS + tid * 4;
            float a = (__ldcg(pp + 0) + __ldcg(pp + 1))
                    + (__ldcg(pp + 2) + __ldcg(pp + 3));
            s_pooled[tid] = a * (1.0f / 65536.0f);
        }
        __syncthreads();

        if (tid < 256) {                     // squeeze: 64 -> 4 partials
            const int k = tid & 63;
            const float pk = s_pooled[tid];
            float p0 = pk * s_wdown[0 * 64 + k];
            float p1 = pk * s_wdown[1 * 64 + k];
            float p2 = pk * s_wdown[2 * 64 + k];
            float p3 = pk * s_wdown[3 * 64 + k];
            #pragma unroll
            for (int o = 16; o > 0; o >>= 1) {
                p0 += __shfl_xor_sync(0xFFFFFFFFu, p0, o);
                p1 += __shfl_xor_sync(0xFFFFFFFFu, p1, o);
                p2 += __shfl_xor_sync(0xFFFFFFFFu, p2, o);
                p3 += __shfl_xor_sync(0xFFFFFFFFu, p3, o);
            }
            if ((tid & 31) == 0) {           // warp w covers (batch w>>1, half w&1)
                const int w = tid >> 5;
                s_hp[w][0] = p0; s_hp[w][1] = p1; s_hp[w][2] = p2; s_hp[w][3] = p3;
            }
        }
        __syncthreads();
        if (tid < 16) {                      // combine halves + bias + relu
            const int bl = tid >> 2, m = tid & 3;
            float h = s_hp[bl * 2][m] + s_hp[bl * 2 + 1][m] + s_bdown[m];
            s_h[bl][m] = fmaxf(h, 0.0f);
        }
        __syncthreads();
        if (tid < 256) {                     // excite: 4 -> 64, sigmoid
            const int bl = tid >> 6, c = tid & 63;
            float s = s_bup[c];
            s = fmaf(s_h[bl][0], s_wup[c * 4 + 0], s);
            s = fmaf(s_h[bl][1], s_wup[c * 4 + 1], s);
            s = fmaf(s_h[bl][2], s_wup[c * 4 + 2], s);
            s = fmaf(s_h[bl][3], s_wup[c * 4 + 3], s);
            s_scale[tid] = 1.0f / (1.0f + expf(-s));
        }
        __syncthreads();

        // ================= Phase 3: rescale (dynamic 32 KB units) =========
        for (;;) {
            if (tid == 0) s_u = atomicAdd(&g_ticket_scale[r], 1u);
            __syncthreads();
            const unsigned u = s_u;
            __syncthreads();
            if (u >= SCALE_UNITS) break;

            const int   pl   = u >> 3;              // round-local plane
            const float s    = s_scale[pl];
            const size_t base = ((size_t)(r * PLANES_PER_RND + pl) << 14)
                              + ((size_t)(u & 7) << 11);
            #pragma unroll
            for (int i = 0; i < 4; i++) {
                const size_t idx = base + tid + (size_t)i * NTHREADS;
                float4 v = __ldcg(px + idx);        // L2 hit from this round's pool
                v.x *= s; v.y *= s; v.z *= s; v.w *= s;
                __stcs(py + idx, v);                // evict-first: protect reads
            }
        }
        // No barrier: round r+1 touches disjoint planes / counter slots.
    }
}

extern "C" void kernel_launch(void* const* d_in, const int* in_sizes, int n_in,
                              void* d_out, int out_size)
{
    const float* trans_b = (const float*)d_in[0];
    const float* w_down  = (const float*)d_in[1];
    const float* b_down  = (const float*)d_in[2];
    const float* w_up    = (const float*)d_in[3];
    const float* b_up    = (const float*)d_in[4];
    float* out = (float*)d_out;

    se_fused_kernel<<<NBLOCKS, NTHREADS>>>(trans_b, out, w_down, b_down, w_up, b_up);
}